// round 6
// baseline (speedup 1.0000x reference)
#include <cuda_runtime.h>
#include <cstdint>
#include <cfloat>

// Problem constants
#define BATCH   2
#define SEQ     2048
#define DMODEL  1024
#define NHEADS  16
#define HDIM    64
#define QKV_LD  3072
#define NTOK    (BATCH * SEQ)      // 4096
#define WINDOW  128
#define STRIDE  64

// Scratch (device globals: no allocation allowed)
__device__ float g_qkv[(size_t)NTOK * QKV_LD];    // 4096 x 3072 (fp32 accum)
__device__ float g_y[(size_t)NTOK * DMODEL];      // 4096 x 1024 (tf32-rounded)
__device__ float g_xa[(size_t)NTOK * DMODEL];     // x, tf32-rounded
__device__ float g_wqkv[(size_t)DMODEL * QKV_LD]; // Wqkv, tf32-rounded
__device__ float g_wp[(size_t)DMODEL * DMODEL];   // Wproj, tf32-rounded

__device__ __forceinline__ unsigned f2tf(float f) {
    unsigned u;
    asm("cvt.rna.tf32.f32 %0, %1;" : "=r"(u) : "f"(f));
    return u;
}
__device__ __forceinline__ float4 cvt4(float4 v) {
    float4 t;
    t.x = __uint_as_float(f2tf(v.x));
    t.y = __uint_as_float(f2tf(v.y));
    t.z = __uint_as_float(f2tf(v.z));
    t.w = __uint_as_float(f2tf(v.w));
    return t;
}

// ---------------------------------------------------------------------------
// tf32 pre-round: out[i] = rna_tf32(in[i])   (vectorized, grid-stride)
// ---------------------------------------------------------------------------
__global__ __launch_bounds__(256) void cvt_tf32(
    const float4* __restrict__ in, float4* __restrict__ out, int n4)
{
    for (int i = blockIdx.x * blockDim.x + threadIdx.x; i < n4;
         i += gridDim.x * blockDim.x)
        out[i] = cvt4(in[i]);
}

// ===========================================================================
// TF32 mma.sync GEMM v3: cp.async 4-stage pipeline.
// C[M,N] = A[M,K] @ B[K,N]; A,B already tf32-rounded bit patterns.
// CTA tile 256x128, BK=16, 256 threads = 8 warps (4M x 2N), warp tile 64x64.
// Per chunk: issue cp.async for chunk it+3, compute chunk it. One barrier
// per chunk; no register staging, no post-compute STS.
// ===========================================================================
#define BM 256
#define BN 128
#define BK 16
#define AP 20    // A row pitch (floats): 80B stride, ldmatrix conflict-free
#define BP 136   // B row pitch (floats): banks 8k+n distinct for scalar LDS
#define STAGES 4
#define STG_A (BM * AP)          // 5120 floats
#define STG_B (BK * BP)          // 2176 floats
#define GEMM_SMEM (STAGES * (STG_A + STG_B) * (int)sizeof(float))  // 116736 B

__device__ __forceinline__ void cp16(uint32_t dst, const float* src) {
    asm volatile("cp.async.ca.shared.global [%0], [%1], 16;"
                 :: "r"(dst), "l"(src) : "memory");
}

__device__ __forceinline__ void issue_stage(
    const float* __restrict__ A, const float* __restrict__ B,
    float* As, float* Bs, int row0, int col0, int k0, int tid, int N, int K)
{
    const int ar = tid >> 2;             // 0..63
    const int ak = (tid & 3) * 4;        // 0,4,8,12
    const int bk = tid >> 4;             // 0..15
    const int bn = (tid & 15) * 8;       // 0..120
#pragma unroll
    for (int p = 0; p < 4; ++p) {
        uint32_t d = (uint32_t)__cvta_generic_to_shared(&As[(p * 64 + ar) * AP + ak]);
        cp16(d, A + (size_t)(row0 + p * 64 + ar) * K + k0 + ak);
    }
    uint32_t d0 = (uint32_t)__cvta_generic_to_shared(&Bs[bk * BP + bn]);
    uint32_t d1 = (uint32_t)__cvta_generic_to_shared(&Bs[bk * BP + bn + 4]);
    const float* bp = B + (size_t)(k0 + bk) * N + col0 + bn;
    cp16(d0, bp);
    cp16(d1, bp + 4);
}

__global__ __launch_bounds__(256, 1) void tgemm(
    const float* __restrict__ A, const float* __restrict__ B,
    float* __restrict__ C, int M, int N, int K)
{
    extern __shared__ float sm[];
    float* As0 = sm;                       // [STAGES][STG_A]
    float* Bs0 = sm + STAGES * STG_A;      // [STAGES][STG_B]

    const int tid  = threadIdx.x;
    const int lane = tid & 31;
    const int wid  = tid >> 5;
    const int warp_m = wid >> 1;           // 0..3
    const int warp_n = wid & 1;            // 0..1
    const int row0 = blockIdx.y * BM;
    const int col0 = blockIdx.x * BN;

    float acc[4][8][4];
#pragma unroll
    for (int mi = 0; mi < 4; ++mi)
#pragma unroll
        for (int ni = 0; ni < 8; ++ni)
#pragma unroll
            for (int e = 0; e < 4; ++e) acc[mi][ni][e] = 0.0f;

    const int nk = K / BK;

    // prologue: issue STAGES-1 chunks
#pragma unroll
    for (int s = 0; s < STAGES - 1; ++s) {
        issue_stage(A, B, As0 + s * STG_A, Bs0 + s * STG_B,
                    row0, col0, s * BK, tid, N, K);
        asm volatile("cp.async.commit_group;" ::: "memory");
    }

    const int lrow = lane & 15;
    const int lk4  = (lane & 16) ? 4 : 0;
    const int bkr  = lane & 3;
    const int bnc  = warp_n * 64 + (lane >> 2);

    for (int it = 0; it < nk; ++it) {
        const int cur = it & (STAGES - 1);

        asm volatile("cp.async.wait_group 2;" ::: "memory");
        __syncthreads();

        // issue chunk it+3 into the buffer freed by chunk it-1
        if (it + STAGES - 1 < nk) {
            const int nb = (it + STAGES - 1) & (STAGES - 1);
            issue_stage(A, B, As0 + nb * STG_A, Bs0 + nb * STG_B,
                        row0, col0, (it + STAGES - 1) * BK, tid, N, K);
        }
        asm volatile("cp.async.commit_group;" ::: "memory");

        // ---- compute chunk it ----
        const float*   Ac  = As0 + cur * STG_A;
        const float*   Bc  = Bs0 + cur * STG_B;
        const unsigned smA = (unsigned)__cvta_generic_to_shared(Ac);
#pragma unroll
        for (int ks = 0; ks < 2; ++ks) {
            unsigned a[4][4];
#pragma unroll
            for (int mi = 0; mi < 4; ++mi) {
                unsigned ad = smA +
                    (((warp_m * 64 + mi * 16 + lrow) * AP + ks * 8 + lk4) << 2);
                asm volatile(
                    "ldmatrix.sync.aligned.m8n8.x4.shared.b16 {%0,%1,%2,%3}, [%4];"
                    : "=r"(a[mi][0]), "=r"(a[mi][1]), "=r"(a[mi][2]), "=r"(a[mi][3])
                    : "r"(ad));
            }
            unsigned b0[8], b1[8];
            const int krow = ks * 8 + bkr;
#pragma unroll
            for (int ni = 0; ni < 8; ++ni) {
                b0[ni] = __float_as_uint(Bc[krow * BP + bnc + ni * 8]);
                b1[ni] = __float_as_uint(Bc[(krow + 4) * BP + bnc + ni * 8]);
            }
#pragma unroll
            for (int mi = 0; mi < 4; ++mi)
#pragma unroll
                for (int ni = 0; ni < 8; ++ni) {
                    asm volatile(
                        "mma.sync.aligned.m16n8k8.row.col.f32.tf32.tf32.f32 "
                        "{%0,%1,%2,%3}, {%4,%5,%6,%7}, {%8,%9}, {%0,%1,%2,%3};"
                        : "+f"(acc[mi][ni][0]), "+f"(acc[mi][ni][1]),
                          "+f"(acc[mi][ni][2]), "+f"(acc[mi][ni][3])
                        : "r"(a[mi][0]), "r"(a[mi][1]), "r"(a[mi][2]), "r"(a[mi][3]),
                          "r"(b0[ni]), "r"(b1[ni]));
                }
        }
    }

    // ---- epilogue ----
    const int g  = lane >> 2;
    const int tg = lane & 3;
#pragma unroll
    for (int mi = 0; mi < 4; ++mi) {
#pragma unroll
        for (int ni = 0; ni < 8; ++ni) {
            const int row = row0 + warp_m * 64 + mi * 16 + g;
            const int col = col0 + warp_n * 64 + ni * 8 + 2 * tg;
            *(float2*)&C[(size_t)row * N + col] =
                make_float2(acc[mi][ni][0], acc[mi][ni][1]);
            *(float2*)&C[(size_t)(row + 8) * N + col] =
                make_float2(acc[mi][ni][2], acc[mi][ni][3]);
        }
    }
}

// ---------------------------------------------------------------------------
// Sparse flash attention (R1 logic; epilogue writes tf32-rounded y).
// ---------------------------------------------------------------------------
#define APITCH 68
#define ATTN_SMEM (4 * 64 * APITCH * (int)sizeof(float))

__global__ __launch_bounds__(256) void sparse_attn(
    const float* __restrict__ qkv, float* __restrict__ y)
{
    extern __shared__ float smf[];
    float* Qt = smf;
    float* Kt = Qt + 64 * APITCH;
    float* Vs = Kt + 64 * APITCH;
    float* Ps = Vs + 64 * APITCH;

    const int t   = blockIdx.x;
    const int h   = blockIdx.y;
    const int b   = blockIdx.z;
    const int tid = threadIdx.x;
    const int tx  = tid & 15;
    const int ty  = tid >> 4;
    const int r0  = t * 64;

    const size_t base = (size_t)b * SEQ * QKV_LD;

    for (int e = tid; e < 1024; e += 256) {
        const int tok = e >> 4;
        const int d4  = (e & 15) * 4;
        float4 v = *(const float4*)(qkv + base + (size_t)(r0 + tok) * QKV_LD + h * HDIM + d4);
        Qt[(d4 + 0) * APITCH + tok] = v.x;
        Qt[(d4 + 1) * APITCH + tok] = v.y;
        Qt[(d4 + 2) * APITCH + tok] = v.z;
        Qt[(d4 + 3) * APITCH + tok] = v.w;
    }

    float m_i[4], l_i[4], acc[4][4];
#pragma unroll
    for (int i = 0; i < 4; ++i) {
        m_i[i] = -3.0e38f;
        l_i[i] = 0.0f;
#pragma unroll
        for (int j = 0; j < 4; ++j) acc[i][j] = 0.0f;
    }

    const int kb_start = (t >= 2) ? (t - 2) : 0;
    const int n_win    = t - kb_start + 1;
    const int nglob    = (t >= 3) ? (t - 2) : 0;
    const int n_tiles  = n_win + (nglob > 0 ? 1 : 0);

    for (int it = 0; it < n_tiles; ++it) {
        const bool is_glob = (it == n_win);
        const int  kcol0   = (kb_start + it) * 64;

        __syncthreads();

        for (int e = tid; e < 1024; e += 256) {
            const int tok = e >> 4;
            const int d4  = (e & 15) * 4;
            int key;
            bool valid;
            if (is_glob) { key = tok * STRIDE; valid = (tok < nglob); }
            else         { key = kcol0 + tok;  valid = true; }
            float4 kv, vv;
            if (valid) {
                const float* kp = qkv + base + (size_t)key * QKV_LD + DMODEL + h * HDIM + d4;
                kv = *(const float4*)kp;
                vv = *(const float4*)(kp + DMODEL);
            } else {
                kv = make_float4(0.f, 0.f, 0.f, 0.f);
                vv = kv;
            }
            Kt[(d4 + 0) * APITCH + tok] = kv.x;
            Kt[(d4 + 1) * APITCH + tok] = kv.y;
            Kt[(d4 + 2) * APITCH + tok] = kv.z;
            Kt[(d4 + 3) * APITCH + tok] = kv.w;
            *(float4*)&Vs[tok * APITCH + d4] = vv;
        }
        __syncthreads();

        float s[4][4];
#pragma unroll
        for (int i = 0; i < 4; ++i)
#pragma unroll
            for (int j = 0; j < 4; ++j) s[i][j] = 0.0f;

#pragma unroll 8
        for (int k = 0; k < 64; ++k) {
            float4 q4 = *(const float4*)&Qt[k * APITCH + ty * 4];
            float4 k4 = *(const float4*)&Kt[k * APITCH + tx * 4];
            float qa[4] = {q4.x, q4.y, q4.z, q4.w};
            float ka[4] = {k4.x, k4.y, k4.z, k4.w};
#pragma unroll
            for (int i = 0; i < 4; ++i)
#pragma unroll
                for (int j = 0; j < 4; ++j)
                    s[i][j] = fmaf(qa[i], ka[j], s[i][j]);
        }

#pragma unroll
        for (int i = 0; i < 4; ++i) {
            const int row = r0 + ty * 4 + i;
#pragma unroll
            for (int j = 0; j < 4; ++j) {
                bool ok;
                if (is_glob) {
                    ok = (tx * 4 + j) < nglob;
                } else {
                    const int col = kcol0 + tx * 4 + j;
                    ok = (col <= row) && ((row - col) <= (WINDOW - 1) || (col & (STRIDE - 1)) == 0);
                }
                s[i][j] = ok ? s[i][j] * 0.125f : -3.0e38f;
            }
        }

#pragma unroll
        for (int i = 0; i < 4; ++i) {
            float mx = fmaxf(fmaxf(s[i][0], s[i][1]), fmaxf(s[i][2], s[i][3]));
#pragma unroll
            for (int off = 8; off >= 1; off >>= 1)
                mx = fmaxf(mx, __shfl_xor_sync(0xffffffffu, mx, off, 16));
            const float mnew = fmaxf(m_i[i], mx);
            const float alpha = __expf(m_i[i] - mnew);
            float rs = 0.0f;
#pragma unroll
            for (int j = 0; j < 4; ++j) {
                const float p = __expf(s[i][j] - mnew);
                Ps[(ty * 4 + i) * APITCH + tx * 4 + j] = p;
                rs += p;
            }
#pragma unroll
            for (int off = 8; off >= 1; off >>= 1)
                rs += __shfl_xor_sync(0xffffffffu, rs, off, 16);
            l_i[i] = l_i[i] * alpha + rs;
            m_i[i] = mnew;
#pragma unroll
            for (int j = 0; j < 4; ++j) acc[i][j] *= alpha;
        }
        __syncthreads();

#pragma unroll 8
        for (int j = 0; j < 64; ++j) {
            float4 v4 = *(const float4*)&Vs[j * APITCH + tx * 4];
            float va[4] = {v4.x, v4.y, v4.z, v4.w};
            float pa[4];
#pragma unroll
            for (int i = 0; i < 4; ++i) pa[i] = Ps[(ty * 4 + i) * APITCH + j];
#pragma unroll
            for (int i = 0; i < 4; ++i)
#pragma unroll
                for (int d = 0; d < 4; ++d)
                    acc[i][d] = fmaf(pa[i], va[d], acc[i][d]);
        }
    }

    // write y pre-rounded to tf32 (consumed by tf32 proj GEMM via cp.async)
#pragma unroll
    for (int i = 0; i < 4; ++i) {
        const float inv = 1.0f / l_i[i];
        const size_t row = (size_t)b * SEQ + r0 + ty * 4 + i;
        float4 o = cvt4(make_float4(acc[i][0] * inv, acc[i][1] * inv,
                                    acc[i][2] * inv, acc[i][3] * inv));
        *(float4*)&y[row * DMODEL + h * HDIM + tx * 4] = o;
    }
}

// ---------------------------------------------------------------------------
extern "C" void kernel_launch(void* const* d_in, const int* in_sizes, int n_in,
                              void* d_out, int out_size)
{
    const float* x     = (const float*)d_in[0];
    const float* Wqkv  = (const float*)d_in[1];
    const float* Wproj = (const float*)d_in[2];
    float* out = (float*)d_out;

    float *qkv = nullptr, *y = nullptr, *xa = nullptr, *wqkv = nullptr, *wp = nullptr;
    cudaGetSymbolAddress((void**)&qkv, g_qkv);
    cudaGetSymbolAddress((void**)&y, g_y);
    cudaGetSymbolAddress((void**)&xa, g_xa);
    cudaGetSymbolAddress((void**)&wqkv, g_wqkv);
    cudaGetSymbolAddress((void**)&wp, g_wp);

    cudaFuncSetAttribute(tgemm, cudaFuncAttributeMaxDynamicSharedMemorySize, GEMM_SMEM);
    cudaFuncSetAttribute(sparse_attn, cudaFuncAttributeMaxDynamicSharedMemorySize, ATTN_SMEM);

    // 0) pre-round inputs to tf32 bit patterns
    cvt_tf32<<<592, 256>>>((const float4*)x,     (float4*)xa,   NTOK * DMODEL / 4);
    cvt_tf32<<<592, 256>>>((const float4*)Wqkv,  (float4*)wqkv, DMODEL * QKV_LD / 4);
    cvt_tf32<<<592, 256>>>((const float4*)Wproj, (float4*)wp,   DMODEL * DMODEL / 4);

    // 1) QKV projection: [4096,1024] @ [1024,3072]
    tgemm<<<dim3(QKV_LD / BN, NTOK / BM), 256, GEMM_SMEM>>>(xa, wqkv, qkv, NTOK, QKV_LD, DMODEL);

    // 2) Sparse attention (writes tf32-rounded y)
    sparse_attn<<<dim3(SEQ / 64, NHEADS, BATCH), 256, ATTN_SMEM>>>(qkv, y);

    // 3) Output projection: [4096,1024] @ [1024,1024]
    tgemm<<<dim3(DMODEL / BN, NTOK / BM), 256, GEMM_SMEM>>>(y, wp, out, NTOK, DMODEL, DMODEL);
}